// round 4
// baseline (speedup 1.0000x reference)
#include <cuda_runtime.h>
#include <cuda_bf16.h>
#include <cstdint>

// C[b] = A[b](1024x64) @ B[b](64x1024), fp32, b in [0,24).
// mma.sync bf16 (m16n8k16) with 2-term bf16 split: acc = a0b0 + a1b0 + a0b1.
// Fused single-pass mainloop: each fragment loaded from smem exactly once.
// CTA tile 128x128, full K=64 in smem. 256 threads = 8 warps, warp tile 32x64.

#define M_DIM 1024
#define N_DIM 1024
#define K_DIM 64
#define BATCH 24
#define BM 128
#define BN 128
#define THREADS 256

// smem: 4 tiles of 128 rows x 64 bf16 (= 128B/row, SW128-swizzled), 16 KB each
#define SMEM_A0 0
#define SMEM_A1 16384
#define SMEM_B0 32768
#define SMEM_B1 49152
#define SMEM_TOTAL 65536

#define SW128(o) ((o) ^ (((o) >> 3) & 0x70))

__device__ __forceinline__ uint32_t smem_u32(const void* p) {
    uint32_t a;
    asm("{ .reg .u64 t; cvta.to.shared.u64 t, %1; cvt.u32.u64 %0, t; }"
        : "=r"(a) : "l"(p));
    return a;
}

__device__ __forceinline__ void ldsm_x4(uint32_t* r, uint32_t addr) {
    asm volatile("ldmatrix.sync.aligned.m8n8.x4.shared.b16 {%0,%1,%2,%3}, [%4];"
                 : "=r"(r[0]), "=r"(r[1]), "=r"(r[2]), "=r"(r[3])
                 : "r"(addr));
}

__device__ __forceinline__ void mma_bf16(float* c, const uint32_t* a,
                                         uint32_t b0, uint32_t b1) {
    asm volatile(
        "mma.sync.aligned.m16n8k16.row.col.f32.bf16.bf16.f32 "
        "{%0,%1,%2,%3}, {%4,%5,%6,%7}, {%8,%9}, {%0,%1,%2,%3};"
        : "+f"(c[0]), "+f"(c[1]), "+f"(c[2]), "+f"(c[3])
        : "r"(a[0]), "r"(a[1]), "r"(a[2]), "r"(a[3]), "r"(b0), "r"(b1));
}

__device__ __forceinline__ uint32_t pack2(__nv_bfloat16 lo, __nv_bfloat16 hi) {
    return (uint32_t)__bfloat16_as_ushort(lo) |
           ((uint32_t)__bfloat16_as_ushort(hi) << 16);
}

__device__ __forceinline__ void split_bf16(float v, __nv_bfloat16& h, __nv_bfloat16& l) {
    h = __float2bfloat16(v);
    l = __float2bfloat16(v - __bfloat162float(h));
}

__global__ void __launch_bounds__(THREADS, 2)
bmm_hmma_kernel(const float* __restrict__ A,
                const float* __restrict__ B,
                float* __restrict__ C) {
    extern __shared__ __align__(1024) char smem[];
    const uint32_t smem_base = smem_u32(smem);
    const int tid = threadIdx.x;
    const int wid = tid >> 5;
    const int lid = tid & 31;

    const int bz   = blockIdx.z;
    const int row0 = blockIdx.y * BM;
    const int col0 = blockIdx.x * BN;

    const float* __restrict__ Ab = A + (size_t)bz * M_DIM * K_DIM;
    const float* __restrict__ Bb = B + (size_t)bz * K_DIM * N_DIM;
    float*       __restrict__ Cb = C + (size_t)bz * M_DIM * N_DIM;

    // ---- A tile: [128 m][64 k] fp32 -> bf16 hi/lo smem (row-major, SW128) ----
#pragma unroll
    for (int i = 0; i < 8; i++) {
        const int f = tid + i * THREADS;
        const int r = f >> 4;
        const int q = f & 15;
        float4 v = *reinterpret_cast<const float4*>(
            &Ab[(size_t)(row0 + r) * K_DIM + q * 4]);
        __nv_bfloat16 hx, lx, hy, ly, hz, lz, hw, lw;
        split_bf16(v.x, hx, lx); split_bf16(v.y, hy, ly);
        split_bf16(v.z, hz, lz); split_bf16(v.w, hw, lw);
        uint2 hi = make_uint2(pack2(hx, hy), pack2(hz, hw));
        uint2 lo = make_uint2(pack2(lx, ly), pack2(lz, lw));
        const uint32_t off = SW128((uint32_t)(r * 128 + q * 8));
        *reinterpret_cast<uint2*>(smem + SMEM_A0 + off) = hi;
        *reinterpret_cast<uint2*>(smem + SMEM_A1 + off) = lo;
    }

    // ---- B tile: global [64 k][128 n] -> smem BT[n][k] bf16 hi/lo ----
    {
        const int n  = tid & 127;
        const int kh = (tid >> 7) * 32;
        const float* bcol = Bb + col0 + n;
#pragma unroll
        for (int k8 = 0; k8 < 4; k8++) {
            float v[8];
#pragma unroll
            for (int j = 0; j < 8; j++)
                v[j] = bcol[(size_t)(kh + k8 * 8 + j) * N_DIM];
            __nv_bfloat16 h[8], l[8];
#pragma unroll
            for (int j = 0; j < 8; j++) split_bf16(v[j], h[j], l[j]);
            uint4 hi, lo;
            hi.x = pack2(h[0], h[1]); hi.y = pack2(h[2], h[3]);
            hi.z = pack2(h[4], h[5]); hi.w = pack2(h[6], h[7]);
            lo.x = pack2(l[0], l[1]); lo.y = pack2(l[2], l[3]);
            lo.z = pack2(l[4], l[5]); lo.w = pack2(l[6], l[7]);
            const uint32_t off = SW128((uint32_t)(n * 128 + (kh + k8 * 8) * 2));
            *reinterpret_cast<uint4*>(smem + SMEM_B0 + off) = hi;
            *reinterpret_cast<uint4*>(smem + SMEM_B1 + off) = lo;
        }
    }

    __syncthreads();

    // ---- warp tiling: warp_m = wid%4 (32 rows), warp_n = wid/4 (64 cols) ----
    const int warp_m = wid & 3;
    const int warp_n = wid >> 2;

    // ldmatrix per-lane address pieces
    const int g = lid >> 3;
    const int r8 = lid & 7;
    const int a_row_l = warp_m * 32 + (g & 1) * 8 + r8;
    const int a_kb_l  = (g >> 1) * 16;
    const int b_row_l = warp_n * 64 + (g >> 1) * 8 + r8;
    const int b_kb_l  = (g & 1) * 16;

    float acc[2][8][4];
#pragma unroll
    for (int mi = 0; mi < 2; mi++)
#pragma unroll
        for (int ni = 0; ni < 8; ni++)
#pragma unroll
            for (int j = 0; j < 4; j++) acc[mi][ni][j] = 0.0f;

    // ---- fused mainloop: each fragment loaded exactly once per k-step ----
#pragma unroll
    for (int ks = 0; ks < 4; ks++) {
        const uint32_t a_off = SW128((uint32_t)(a_row_l * 128 + ks * 32 + a_kb_l));
        const uint32_t b_off = SW128((uint32_t)(b_row_l * 128 + ks * 32 + b_kb_l));
        const uint32_t a_off2 =
            SW128((uint32_t)((a_row_l + 16) * 128 + ks * 32 + a_kb_l));

        // B0 fragments (16 regs)
        uint32_t b0f[8][2];
#pragma unroll
        for (int nq = 0; nq < 4; nq++) {
            uint32_t rr[4];
            ldsm_x4(rr, smem_base + SMEM_B0 +
                        SW128((uint32_t)((b_row_l + nq * 16) * 128 + ks * 32 + b_kb_l)));
            b0f[nq * 2 + 0][0] = rr[0]; b0f[nq * 2 + 0][1] = rr[1];
            b0f[nq * 2 + 1][0] = rr[2]; b0f[nq * 2 + 1][1] = rr[3];
        }
        // A0 fragments (8 regs)
        uint32_t a0f[2][4];
        ldsm_x4(a0f[0], smem_base + SMEM_A0 + a_off);
        ldsm_x4(a0f[1], smem_base + SMEM_A0 + a_off2);
        // A1 fragments (8 regs)
        uint32_t a1f[2][4];
        ldsm_x4(a1f[0], smem_base + SMEM_A1 + a_off);
        ldsm_x4(a1f[1], smem_base + SMEM_A1 + a_off2);

        // a0*b0 and a1*b0 (B0 and A1 die after this)
#pragma unroll
        for (int mi = 0; mi < 2; mi++)
#pragma unroll
            for (int ni = 0; ni < 8; ni++)
                mma_bf16(acc[mi][ni], a0f[mi], b0f[ni][0], b0f[ni][1]);
#pragma unroll
        for (int mi = 0; mi < 2; mi++)
#pragma unroll
            for (int ni = 0; ni < 8; ni++)
                mma_bf16(acc[mi][ni], a1f[mi], b0f[ni][0], b0f[ni][1]);

        // B1 fragments (reuses B0's registers after it dies)
        uint32_t b1f[8][2];
#pragma unroll
        for (int nq = 0; nq < 4; nq++) {
            uint32_t rr[4];
            ldsm_x4(rr, smem_base + SMEM_B1 +
                        SW128((uint32_t)((b_row_l + nq * 16) * 128 + ks * 32 + b_kb_l)));
            b1f[nq * 2 + 0][0] = rr[0]; b1f[nq * 2 + 0][1] = rr[1];
            b1f[nq * 2 + 1][0] = rr[2]; b1f[nq * 2 + 1][1] = rr[3];
        }
        // a0*b1
#pragma unroll
        for (int mi = 0; mi < 2; mi++)
#pragma unroll
            for (int ni = 0; ni < 8; ni++)
                mma_bf16(acc[mi][ni], a0f[mi], b1f[ni][0], b1f[ni][1]);
    }

    // ---- epilogue: direct stores ----
    const int tq = lid & 3;
    const int tr = lid >> 2;
#pragma unroll
    for (int mi = 0; mi < 2; mi++) {
        const int rbase = row0 + warp_m * 32 + mi * 16 + tr;
        float* c0 = &Cb[(size_t)rbase * N_DIM + col0 + warp_n * 64 + tq * 2];
        float* c1 = c0 + 8 * N_DIM;
#pragma unroll
        for (int ni = 0; ni < 8; ni++) {
            float2 v0 = make_float2(acc[mi][ni][0], acc[mi][ni][1]);
            float2 v1 = make_float2(acc[mi][ni][2], acc[mi][ni][3]);
            *reinterpret_cast<float2*>(c0 + ni * 8) = v0;
            *reinterpret_cast<float2*>(c1 + ni * 8) = v1;
        }
    }
}

extern "C" void kernel_launch(void* const* d_in, const int* in_sizes, int n_in,
                              void* d_out, int out_size) {
    const float* A = (const float*)d_in[0];   // [2,12,1024,64]
    const float* B = (const float*)d_in[1];   // [2,12,64,1024]
    float* C = (float*)d_out;                 // [2,12,1024,1024]

    cudaFuncSetAttribute(bmm_hmma_kernel,
                         cudaFuncAttributeMaxDynamicSharedMemorySize, SMEM_TOTAL);
    dim3 grid(N_DIM / BN, M_DIM / BM, BATCH);  // (8, 8, 24)
    bmm_hmma_kernel<<<grid, THREADS, SMEM_TOTAL>>>(A, B, C);
}